// round 3
// baseline (speedup 1.0000x reference)
#include <cuda_runtime.h>

#define Bv 1024
#define Tv 512
#define Kv 48
#define BPB 2                  // batches per block
#define TPB (BPB * Kv)         // 96 threads = 3 full warps, zero idle lanes

// Forward algorithm in scaled-linear space with S = s_0 renormalization:
//   alpha_t(j) = c + log s_j
//   step: u_j = (sum_i s_i * E_ij) * exp(e_tj) / S,  S = s_0,  c += log S
//   E = exp(trans), column j held in registers by thread j. Exact algebra;
//   per-step rescale keeps everything comfortably inside fp32 range
//   (|trans|<=0.25 so E in [0.78,1.28]; per-step spread ~exp(|e_j - e_0|)).
__global__ void __launch_bounds__(TPB, 4) crf_fwd_kernel(
    const float* __restrict__ emis,    // [B,T,K]
    const float* __restrict__ trans,   // [K,K]
    float* __restrict__ out)           // [B]
{
    __shared__ __align__(16) float sA[2][BPB][Kv];   // double-buffered alpha rows

    const int tid = threadIdx.x;
    const int bl  = tid / Kv;          // batch within block (0..1)
    const int j   = tid - bl * Kv;     // state 0..47
    const int b   = blockIdx.x * BPB + bl;

    // E column j in registers: E[i][j] = exp(trans[i][j])
    float Ecol[Kv];
    #pragma unroll
    for (int i = 0; i < Kv; i++) Ecol[i] = __expf(trans[i * Kv + j]);

    const float* eb = emis + (size_t)b * Tv * Kv + j;

    // ---- t = 0: s_j = exp(e0_j), c = 0 ----
    float s = __expf(eb[0]);
    float c = 0.0f;

    // two-deep emission prefetch (hide ~400-600 cyc DRAM latency)
    float e_cur = eb[Kv];
    float e_nxt = eb[2 * Kv];

    int buf = 0;
    for (int t = 1; t < Tv; t++) {
        float e_fut = (t + 2 < Tv) ? eb[(size_t)(t + 2) * Kv] : 0.0f;

        float ex = __expf(e_cur);          // pre-barrier: off the critical path
        sA[buf][bl][j] = s;
        __syncthreads();                   // the ONLY barrier per step

        float S    = sA[buf][bl][0];       // batch-uniform scale = s_0 > 0
        // scalar chain (MUFU) runs concurrently with the FMA tree below
        float invS = __fdividef(1.0f, S);
        c += __logf(S);

        float u0 = 0.f, u1 = 0.f, u2 = 0.f, u3 = 0.f;
        const float4* av = (const float4*)sA[buf][bl];  // 192B row, 16B aligned
        #pragma unroll
        for (int i = 0; i < Kv / 4; i++) {
            float4 a4 = av[i];                          // LDS.128 broadcast
            u0 = fmaf(a4.x, Ecol[4 * i + 0], u0);
            u1 = fmaf(a4.y, Ecol[4 * i + 1], u1);
            u2 = fmaf(a4.z, Ecol[4 * i + 2], u2);
            u3 = fmaf(a4.w, Ecol[4 * i + 3], u3);
        }
        s = ((u0 + u1) + (u2 + u3)) * (ex * invS);

        buf ^= 1;
        e_cur = e_nxt;
        e_nxt = e_fut;
    }

    // ---- final: log_norm = c + log(sum_j s_j) ----
    sA[buf][bl][j] = s;
    __syncthreads();
    if (j == 0) {
        const float4* av = (const float4*)sA[buf][bl];
        float4 t0 = av[0];
        float acc0 = t0.x + t0.y + t0.z + t0.w;
        #pragma unroll
        for (int i = 1; i < Kv / 4; i++) {
            float4 a4 = av[i];
            acc0 += (a4.x + a4.y) + (a4.z + a4.w);
        }
        out[b] = c + __logf(acc0);
    }
}

// Sequence score: unary gathers + binary transition lookups; one warp per batch.
// Runs after the forward kernel and subtracts the score in place.
__global__ void __launch_bounds__(256) crf_score_kernel(
    const float* __restrict__ emis,
    const int* __restrict__ labels,    // [B,T]
    const float* __restrict__ trans,
    float* __restrict__ out)
{
    int warp = (blockIdx.x * blockDim.x + threadIdx.x) >> 5;
    int lane = threadIdx.x & 31;
    if (warp >= Bv) return;
    const float* eb = emis + (size_t)warp * Tv * Kv;
    const int*   lb = labels + (size_t)warp * Tv;

    float acc = 0.0f;
    for (int t = lane; t < Tv; t += 32) {
        int lt = lb[t];
        acc += eb[(size_t)t * Kv + lt];
        if (t + 1 < Tv) acc += trans[lt * Kv + lb[t + 1]];
    }
    #pragma unroll
    for (int o = 16; o; o >>= 1) acc += __shfl_xor_sync(0xffffffffu, acc, o);
    if (lane == 0) out[warp] -= acc;
}

extern "C" void kernel_launch(void* const* d_in, const int* in_sizes, int n_in,
                              void* d_out, int out_size) {
    const float* emis   = (const float*)d_in[0];   // output: [B,T,K] fp32
    const int*   labels = (const int*)d_in[1];     // label_input: [B,T] int32
    const float* trans  = (const float*)d_in[2];   // transition_params: [K,K] fp32
    float* out = (float*)d_out;                    // [B] fp32

    crf_fwd_kernel<<<Bv / BPB, TPB>>>(emis, trans, out);
    crf_score_kernel<<<Bv / 8, 256>>>(emis, labels, trans, out);
}